// round 16
// baseline (speedup 1.0000x reference)
#include <cuda_runtime.h>
#include <cuda_bf16.h>
#include <stdint.h>

#define NN 100000
#define NE 1600000
#define NG 64

typedef unsigned int uint32;

// ---------------- static device scratch (zero-initialized at load; restored each run) ----------------
static __device__ float g_deg[NN];
static __device__ int   g_cnti[NN];
static __device__ int   g_rowptr[NN + 1];
static __device__ int   g_offs[NN];
static __device__ int   g_bsum[512];
static __device__ int   g_is64;
static __device__ int2  g_csr[NE];                 // packed {src, w_bits}
static __device__ float g_G[(size_t)NN * 192];
static __device__ float g_TA[(size_t)NN * 64];
static __device__ float g_TB[(size_t)NN * 64];
static __device__ float g_H1[(size_t)NN * 64];
static __device__ float g_H2[(size_t)NN * 64];
static __device__ float g_sums[NG * 128];
static __device__ float g_cnt[NG];
static __device__ float g_Wb1[128 * 192];
static __device__ float g_Ws1[128 * 192];
static __device__ float g_Wb2[192 * 64];
static __device__ float g_Ws2[192 * 64];
static __device__ float g_Wb3[192 * 128];
static __device__ float g_Ws3[192 * 128];

// ---------------- helpers ----------------
__device__ __forceinline__ long ldidx(const void* p, long i, int is64) {
    if (is64) return (long)((const long long*)p)[i];
    return (long)((const int*)p)[i];
}

// Detect int64 vs int32 from edge_index words (uniform random values -> safe).
// NEVER call on `batch` (sorted, leading zeros break the heuristic).
__device__ __forceinline__ int detect64(const unsigned int* w) {
    int is64 = 1;
    for (int i = 0; i < 128; i++) {
        if (w[2 * i + 1] != 0u) { is64 = 0; break; }
    }
    return is64;
}

__device__ __forceinline__ float rinv(float d) { return (d > 0.0f) ? rsqrtf(d) : 0.0f; }

__device__ __forceinline__ void redAdd2(float* p, float x, float y) {
    asm volatile("red.global.add.v2.f32 [%0], {%1, %2};"
                 :: "l"(p), "f"(x), "f"(y) : "memory");
}

__device__ __forceinline__ uint32 tf32r(float f) {
    uint32 r;
    asm("cvt.rna.tf32.f32 %0, %1;" : "=r"(r) : "f"(f));
    return r;
}

__device__ __forceinline__ void mma_tf32(float* c, const uint32* a, uint32 b0, uint32 b1) {
    asm volatile("mma.sync.aligned.m16n8k8.row.col.f32.tf32.tf32.f32 "
                 "{%0,%1,%2,%3}, {%4,%5,%6,%7}, {%8,%9}, {%0,%1,%2,%3};"
                 : "+f"(c[0]), "+f"(c[1]), "+f"(c[2]), "+f"(c[3])
                 : "r"(a[0]), "r"(a[1]), "r"(a[2]), "r"(a[3]), "r"(b0), "r"(b1));
}

__device__ __forceinline__ void split1(float f, float& fb, float& fs) {
    uint32 tb = tf32r(f);
    fb = __uint_as_float(tb);
    fs = __uint_as_float(tf32r(f - fb));
}

// ---------------- tf32 tensor-core GEMM body (XN=3: full 3xTF32; XN=2: drop A-small term) ----------------
// POOLB: apply bias+relu and pool directly into g_sums/g_cnt, restore deg/cnti invariants.
template <int KTOT, int BN, bool TRIPLE, bool RELUB, bool POOLB, int XN>
__device__ __forceinline__ void gemm_tf32_body(
    int bid, const float* __restrict__ A0, const float* __restrict__ A1,
    const float* __restrict__ A2,
    const float* __restrict__ Wb, const float* __restrict__ Ws,
    const float* __restrict__ bias, float* __restrict__ out,
    const void* __restrict__ batch, int N, int nodeOff) {
    constexpr int BM = 64, BK = 32;
    constexpr int SAS = 36;
    constexpr int SBS = BN + 8;
    constexpr int NA = BN / 32;
    extern __shared__ float sm[];
    float* sAb = sm;
    float* sAs = (XN == 3) ? (sAb + BM * SAS) : sAb;   // unused alias when XN==2
    float* sBb = sAb + (XN == 3 ? 2 : 1) * BM * SAS;
    float* sBs = sBb + BK * SBS;

    const int tid = threadIdx.x;
    const int wid = tid >> 5, lane = tid & 31;
    const int g = lane >> 2, tig = lane & 3;
    const int wm = (wid & 1) * 32;
    const int wn = (wid >> 1) * (BN / 4);
    const int base = nodeOff + bid * BM;

    float acc[2][NA][4];
#pragma unroll
    for (int ma = 0; ma < 2; ma++)
#pragma unroll
        for (int j = 0; j < NA; j++)
#pragma unroll
            for (int i = 0; i < 4; i++) acc[ma][j][i] = 0.f;

    for (int kc = 0; kc < KTOT; kc += BK) {
        const float* Ap;
        int strideA, colBase;
        if (TRIPLE) {
            const float* Ts[3] = {A0, A1, A2};
            Ap = Ts[kc >> 6]; strideA = 64; colBase = kc & 63;
        } else {
            Ap = A0; strideA = KTOT; colBase = kc;
        }
#pragma unroll
        for (int r = 0; r < 2; r++) {
            int i = tid + r * 256;
            int row = i >> 3, c4 = (i & 7) * 4;
            int node = base + row;
            float4 v = (node < N)
                ? *reinterpret_cast<const float4*>(Ap + (size_t)node * strideA + colBase + c4)
                : make_float4(0.f, 0.f, 0.f, 0.f);
            if (XN == 3) {
                float4 vb, vs;
                split1(v.x, vb.x, vs.x); split1(v.y, vb.y, vs.y);
                split1(v.z, vb.z, vs.z); split1(v.w, vb.w, vs.w);
                *reinterpret_cast<float4*>(&sAb[row * SAS + c4]) = vb;
                *reinterpret_cast<float4*>(&sAs[row * SAS + c4]) = vs;
            } else {
                float4 vb;
                vb.x = __uint_as_float(tf32r(v.x));
                vb.y = __uint_as_float(tf32r(v.y));
                vb.z = __uint_as_float(tf32r(v.z));
                vb.w = __uint_as_float(tf32r(v.w));
                *reinterpret_cast<float4*>(&sAb[row * SAS + c4]) = vb;
            }
        }
#pragma unroll
        for (int i = tid; i < BK * BN / 4; i += 256) {
            int row = i / (BN / 4), c4 = (i % (BN / 4)) * 4;
            *reinterpret_cast<float4*>(&sBb[row * SBS + c4]) =
                *reinterpret_cast<const float4*>(Wb + (size_t)(kc + row) * BN + c4);
            *reinterpret_cast<float4*>(&sBs[row * SBS + c4]) =
                *reinterpret_cast<const float4*>(Ws + (size_t)(kc + row) * BN + c4);
        }
        __syncthreads();
#pragma unroll
        for (int ks = 0; ks < 4; ks++) {
            const int k0 = ks * 8;
            uint32 ab[2][4], as_[2][4];
#pragma unroll
            for (int ma = 0; ma < 2; ma++) {
                const float* pb = &sAb[(wm + ma * 16 + g) * SAS + k0 + tig];
                ab[ma][0] = __float_as_uint(pb[0]);
                ab[ma][1] = __float_as_uint(pb[8 * SAS]);
                ab[ma][2] = __float_as_uint(pb[4]);
                ab[ma][3] = __float_as_uint(pb[8 * SAS + 4]);
                if (XN == 3) {
                    const float* ps = &sAs[(wm + ma * 16 + g) * SAS + k0 + tig];
                    as_[ma][0] = __float_as_uint(ps[0]);
                    as_[ma][1] = __float_as_uint(ps[8 * SAS]);
                    as_[ma][2] = __float_as_uint(ps[4]);
                    as_[ma][3] = __float_as_uint(ps[8 * SAS + 4]);
                }
            }
#pragma unroll
            for (int j = 0; j < NA; j++) {
                int n = wn + j * 8 + g;
                uint32 bb0 = __float_as_uint(sBb[(k0 + tig) * SBS + n]);
                uint32 bb1 = __float_as_uint(sBb[(k0 + tig + 4) * SBS + n]);
                uint32 bs0 = __float_as_uint(sBs[(k0 + tig) * SBS + n]);
                uint32 bs1 = __float_as_uint(sBs[(k0 + tig + 4) * SBS + n]);
#pragma unroll
                for (int ma = 0; ma < 2; ma++) {
                    mma_tf32(acc[ma][j], ab[ma], bs0, bs1);                 // big * small
                    if (XN == 3) mma_tf32(acc[ma][j], as_[ma], bb0, bb1);   // small * big
                    mma_tf32(acc[ma][j], ab[ma], bb0, bb1);                 // big * big
                }
            }
        }
        __syncthreads();
    }

    // ---- epilogue ----
    const int is64 = POOLB ? g_is64 : 0;
#pragma unroll
    for (int ma = 0; ma < 2; ma++) {
        const int n0 = base + wm + ma * 16 + g, n1 = n0 + 8;
        int g0 = -1, g1 = -1;
        if (POOLB) {
            if (n0 < N) g0 = (int)ldidx(batch, n0, is64);
            if (n1 < N) g1 = (int)ldidx(batch, n1, is64);
        }
#pragma unroll
        for (int j = 0; j < NA; j++) {
            int col = wn + j * 8 + tig * 2;
            float c0 = acc[ma][j][0], c1 = acc[ma][j][1], c2 = acc[ma][j][2], c3 = acc[ma][j][3];
            if (RELUB) {
                float b0 = bias[col], b1 = bias[col + 1];
                c0 = fmaxf(c0 + b0, 0.f); c1 = fmaxf(c1 + b1, 0.f);
                c2 = fmaxf(c2 + b0, 0.f); c3 = fmaxf(c3 + b1, 0.f);
            }
            if (POOLB) {
                if (n0 < N) redAdd2(&g_sums[g0 * 128 + col], c0, c1);
                if (n1 < N) redAdd2(&g_sums[g1 * 128 + col], c2, c3);
            } else {
                if (n0 < N) *reinterpret_cast<float2*>(&out[(size_t)n0 * BN + col]) = make_float2(c0, c1);
                if (n1 < N) *reinterpret_cast<float2*>(&out[(size_t)n1 * BN + col]) = make_float2(c2, c3);
            }
        }
        if (POOLB && wn == 0 && tig == 0) {
            if (n0 < N) atomicAdd(&g_cnt[g0], 1.0f);
            if (n1 < N) atomicAdd(&g_cnt[g1], 1.0f);
        }
    }
    if (POOLB) {
        if (tid < BM) {
            int node = base + tid;
            if (node < N) { g_deg[node] = 0.0f; g_cnti[node] = 0; }
        }
    }
}

template <int KTOT, int BN, bool TRIPLE, bool RELUB, bool POOLB, int XN>
__global__ void gemm_tf32_kernel(const float* __restrict__ A0, const float* __restrict__ A1,
                                 const float* __restrict__ A2,
                                 const float* __restrict__ Wb, const float* __restrict__ Ws,
                                 const float* __restrict__ bias, float* __restrict__ out,
                                 const void* __restrict__ batch, int N, int nodeOff) {
    gemm_tf32_body<KTOT, BN, TRIPLE, RELUB, POOLB, XN>(blockIdx.x, A0, A1, A2, Wb, Ws, bias, out,
                                                       batch, N, nodeOff);
}

// ---------------- launch #0: weight transform + tf32 split ----------------
__global__ void wsplit_kernel(const float* __restrict__ W1, const float* __restrict__ W2,
                              const float* __restrict__ W3) {
    int i = blockIdx.x * blockDim.x + threadIdx.x;
    float v;
    float *pb, *ps;
    int idx;
    if (i < 128 * 192) {
        int f = i / 192, n = i % 192, chunk = n >> 6, nc = n & 63;
        const int S = 128 * 64;
        if (chunk == 0)      v = W1[f * 64 + nc] - W1[2 * S + f * 64 + nc];
        else if (chunk == 1) v = W1[S + f * 64 + nc];
        else                 v = 2.f * W1[2 * S + f * 64 + nc];
        pb = g_Wb1; ps = g_Ws1; idx = i;
    } else if (i < 128 * 192 + 192 * 64) {
        int j = i - 128 * 192;
        int k = j / 64, n = j % 64, seg = k / 64, f = k % 64;
        const int S = 64 * 64;
        if (seg == 0)      v = W2[f * 64 + n] - W2[2 * S + f * 64 + n];
        else if (seg == 1) v = W2[S + f * 64 + n];
        else               v = 2.f * W2[2 * S + f * 64 + n];
        pb = g_Wb2; ps = g_Ws2; idx = j;
    } else if (i < 128 * 192 + 192 * 64 + 192 * 128) {
        int j = i - 128 * 192 - 192 * 64;
        int k = j / 128, n = j % 128, seg = k / 64, f = k % 64;
        const int S = 64 * 128;
        if (seg == 0)      v = W3[f * 128 + n] - W3[2 * S + f * 128 + n];
        else if (seg == 1) v = W3[S + f * 128 + n];
        else               v = 2.f * W3[2 * S + f * 128 + n];
        pb = g_Wb3; ps = g_Ws3; idx = j;
    } else return;
    float fb, fs;
    split1(v, fb, fs);
    pb[idx] = fb;
    ps[idx] = fs;
}

// ---------------- launch #1: L1 GEMM half-A + histogram (4 edges/thread) ----------------
__global__ void fused_gemmA_hist(const float* __restrict__ x, float* __restrict__ G, int N,
                                 const void* __restrict__ ei, const float* __restrict__ ea,
                                 long E, int gemmBlocks) {
    if (blockIdx.x < gemmBlocks) {
        gemm_tf32_body<128, 192, false, false, false, 2>(blockIdx.x, x, nullptr, nullptr,
                                                         g_Wb1, g_Ws1, nullptr, G, nullptr, N, 0);
        return;
    }
    __shared__ int s64;
    if (threadIdx.x == 0) {
        s64 = detect64((const unsigned int*)ei);
        if (blockIdx.x == gemmBlocks) g_is64 = s64;   // publish for pooled epilogue
    }
    __syncthreads();
    long eBase = (long)(blockIdx.x - gemmBlocks) * 1024;
#pragma unroll
    for (int k = 0; k < 4; k++) {
        long e = eBase + threadIdx.x + k * 256;
        if (e < E) {
            long src = ldidx(ei, e, s64);
            long dst = ldidx(ei, E + e, s64);
            atomicAdd(&g_deg[src], ea[e]);
            atomicAdd(&g_cnti[dst], 1);
        }
    }
}

// ---------------- launches #2/#3: 2-level exclusive scan (parallel) ----------------
__global__ void scan_local_kernel(int n) {
    __shared__ int sm[256];
    int gid = blockIdx.x * 256 + threadIdx.x;
    int v = (gid < n) ? g_cnti[gid] : 0;
    sm[threadIdx.x] = v;
    __syncthreads();
    for (int off = 1; off < 256; off <<= 1) {
        int t = (threadIdx.x >= off) ? sm[threadIdx.x - off] : 0;
        __syncthreads();
        sm[threadIdx.x] += t;
        __syncthreads();
    }
    if (gid < n) g_rowptr[gid] = sm[threadIdx.x] - v;
    if (threadIdx.x == 255) g_bsum[blockIdx.x] = sm[255];
}

__global__ void scan_finish_kernel(int n, int E) {
    __shared__ int red[256];
    const int bid = blockIdx.x;
    int partial = 0;
    for (int i = threadIdx.x; i < bid; i += 256) partial += g_bsum[i];
    red[threadIdx.x] = partial;
    __syncthreads();
    for (int off = 128; off > 0; off >>= 1) {
        if (threadIdx.x < off) red[threadIdx.x] += red[threadIdx.x + off];
        __syncthreads();
    }
    int offset = red[0];
    int gid = bid * 256 + threadIdx.x;
    if (gid < n) {
        int v = g_rowptr[gid] + offset;
        g_rowptr[gid] = v;
        g_offs[gid] = v;
    }
    if (gid == 0) g_rowptr[n] = E;
}

// ---------------- launch #4: L1 GEMM half-B + CSR scatter (4 edges/thread, packed int2) ----------------
__global__ void fused_gemmB_scatter(const float* __restrict__ x, float* __restrict__ G, int N,
                                    int nodeOff, const void* __restrict__ ei,
                                    const float* __restrict__ ea, long E, int gemmBlocks) {
    if (blockIdx.x < gemmBlocks) {
        gemm_tf32_body<128, 192, false, false, false, 2>(blockIdx.x, x, nullptr, nullptr,
                                                         g_Wb1, g_Ws1, nullptr, G, nullptr, N, nodeOff);
        return;
    }
    __shared__ int s64;
    if (threadIdx.x == 0) s64 = detect64((const unsigned int*)ei);
    __syncthreads();
    long eBase = (long)(blockIdx.x - gemmBlocks) * 1024;
#pragma unroll
    for (int k = 0; k < 4; k++) {
        long e = eBase + threadIdx.x + k * 256;
        if (e < E) {
            int src = (int)ldidx(ei, e, s64);
            int dst = (int)ldidx(ei, E + e, s64);
            int pos = atomicAdd(&g_offs[dst], 1);
            float w = -rinv(g_deg[src]) * ea[e] * rinv(g_deg[dst]);
            g_csr[pos] = make_int2(src, __float_as_int(w));
        }
    }
}

// ---------------- dst-major pull propagation, F=64, unroll-8, occupancy 6 blocks/SM ----------------
template <bool ADD, bool RELUB>
__global__ void __launch_bounds__(256, 6)
prop64_kernel(const float* __restrict__ x, int xs,
              const float* __restrict__ add, int as,
              const float* __restrict__ bias,
              float* __restrict__ out, int N) {
    int t = blockIdx.x * blockDim.x + threadIdx.x;
    int n = t >> 4;
    int c = t & 15;
    if (n >= N) return;
    int p = g_rowptr[n], end = g_rowptr[n + 1];
    float4 a0 = {0.f, 0.f, 0.f, 0.f}, a1 = {0.f, 0.f, 0.f, 0.f};
    float4 a2 = {0.f, 0.f, 0.f, 0.f}, a3 = {0.f, 0.f, 0.f, 0.f};
    for (; p + 8 <= end; p += 8) {
        int2 e0 = __ldg(&g_csr[p]),     e1 = __ldg(&g_csr[p + 1]);
        int2 e2 = __ldg(&g_csr[p + 2]), e3 = __ldg(&g_csr[p + 3]);
        int2 e4 = __ldg(&g_csr[p + 4]), e5 = __ldg(&g_csr[p + 5]);
        int2 e6 = __ldg(&g_csr[p + 6]), e7 = __ldg(&g_csr[p + 7]);
        float4 v0 = __ldg(reinterpret_cast<const float4*>(x + (size_t)e0.x * xs) + c);
        float4 v1 = __ldg(reinterpret_cast<const float4*>(x + (size_t)e1.x * xs) + c);
        float4 v2 = __ldg(reinterpret_cast<const float4*>(x + (size_t)e2.x * xs) + c);
        float4 v3 = __ldg(reinterpret_cast<const float4*>(x + (size_t)e3.x * xs) + c);
        float4 v4 = __ldg(reinterpret_cast<const float4*>(x + (size_t)e4.x * xs) + c);
        float4 v5 = __ldg(reinterpret_cast<const float4*>(x + (size_t)e5.x * xs) + c);
        float4 v6 = __ldg(reinterpret_cast<const float4*>(x + (size_t)e6.x * xs) + c);
        float4 v7 = __ldg(reinterpret_cast<const float4*>(x + (size_t)e7.x * xs) + c);
        float w0 = __int_as_float(e0.y), w1 = __int_as_float(e1.y);
        float w2 = __int_as_float(e2.y), w3 = __int_as_float(e3.y);
        float w4 = __int_as_float(e4.y), w5 = __int_as_float(e5.y);
        float w6 = __int_as_float(e6.y), w7 = __int_as_float(e7.y);
        a0.x += w0 * v0.x; a0.y += w0 * v0.y; a0.z += w0 * v0.z; a0.w += w0 * v0.w;
        a1.x += w1 * v1.x; a1.y += w1 * v1.y; a1.z += w1 * v1.z; a1.w += w1 * v1.w;
        a2.x += w2 * v2.x; a2.y += w2 * v2.y; a2.z += w2 * v2.z; a2.w += w2 * v2.w;
        a3.x += w3 * v3.x; a3.y += w3 * v3.y; a3.z += w3 * v3.z; a3.w += w3 * v3.w;
        a0.x += w4 * v4.x; a0.y += w4 * v4.y; a0.z += w4 * v4.z; a0.w += w4 * v4.w;
        a1.x += w5 * v5.x; a1.y += w5 * v5.y; a1.z += w5 * v5.z; a1.w += w5 * v5.w;
        a2.x += w6 * v6.x; a2.y += w6 * v6.y; a2.z += w6 * v6.z; a2.w += w6 * v6.w;
        a3.x += w7 * v7.x; a3.y += w7 * v7.y; a3.z += w7 * v7.z; a3.w += w7 * v7.w;
    }
    for (; p < end; p++) {
        int2 e0 = __ldg(&g_csr[p]);
        float w0 = __int_as_float(e0.y);
        float4 v0 = __ldg(reinterpret_cast<const float4*>(x + (size_t)e0.x * xs) + c);
        a0.x += w0 * v0.x; a0.y += w0 * v0.y; a0.z += w0 * v0.z; a0.w += w0 * v0.w;
    }
    a0.x += a1.x; a0.y += a1.y; a0.z += a1.z; a0.w += a1.w;
    a2.x += a3.x; a2.y += a3.y; a2.z += a3.z; a2.w += a3.w;
    a0.x += a2.x; a0.y += a2.y; a0.z += a2.z; a0.w += a2.w;
    if (ADD) {
        float4 u = __ldg(reinterpret_cast<const float4*>(add + (size_t)n * as) + c);
        a0.x += u.x; a0.y += u.y; a0.z += u.z; a0.w += u.w;
    }
    if (RELUB) {
        float4 b = *reinterpret_cast<const float4*>(bias + 4 * c);
        a0.x = fmaxf(a0.x + b.x, 0.f);
        a0.y = fmaxf(a0.y + b.y, 0.f);
        a0.z = fmaxf(a0.z + b.z, 0.f);
        a0.w = fmaxf(a0.w + b.w, 0.f);
    }
    reinterpret_cast<float4*>(out + (size_t)n * 64)[c] = a0;
}

// ---------------- final linear + restore sums/cnt to zero ----------------
__global__ void final_kernel(const float* __restrict__ lw, const float* __restrict__ lb,
                             float* __restrict__ out) {
    __shared__ float sp[128];
    int g = blockIdx.x;
    float inv = 1.0f / fmaxf(g_cnt[g], 1.0f);
    for (int i = threadIdx.x; i < 128; i += 32)
        sp[i] = g_sums[g * 128 + i] * inv;
    __syncthreads();
    if (threadIdx.x < 10) {
        float acc = lb[threadIdx.x];
#pragma unroll 8
        for (int f = 0; f < 128; f++)
            acc += sp[f] * lw[f * 10 + threadIdx.x];
        out[g * 10 + threadIdx.x] = acc;
    }
    for (int i = threadIdx.x; i < 128; i += 32)
        g_sums[g * 128 + i] = 0.0f;
    if (threadIdx.x == 0) g_cnt[g] = 0.0f;
}

static inline int cdivl(long a, long b) { return (int)((a + b - 1) / b); }

extern "C" void kernel_launch(void* const* d_in, const int* in_sizes, int n_in,
                              void* d_out, int out_size) {
    const float* x    = (const float*)d_in[0];
    const void*  ei   = d_in[1];
    const float* ea   = (const float*)d_in[2];
    const void*  bat  = d_in[3];
    const float* W1   = (const float*)d_in[4];
    const float* b1   = (const float*)d_in[5];
    const float* W2   = (const float*)d_in[6];
    const float* b2   = (const float*)d_in[7];
    const float* W3   = (const float*)d_in[8];
    const float* b3   = (const float*)d_in[9];
    const float* linW = (const float*)d_in[10];
    const float* linB = (const float*)d_in[11];
    float* out = (float*)d_out;

    const long E = in_sizes[2];
    const long N = in_sizes[3];

    float *pG, *pTA, *pTB, *pH1, *pH2;
    float *pWb2, *pWs2, *pWb3, *pWs3;
    cudaGetSymbolAddress((void**)&pG, g_G);
    cudaGetSymbolAddress((void**)&pTA, g_TA);
    cudaGetSymbolAddress((void**)&pTB, g_TB);
    cudaGetSymbolAddress((void**)&pH1, g_H1);
    cudaGetSymbolAddress((void**)&pH2, g_H2);
    cudaGetSymbolAddress((void**)&pWb2, g_Wb2);
    cudaGetSymbolAddress((void**)&pWs2, g_Ws2);
    cudaGetSymbolAddress((void**)&pWb3, g_Wb3);
    cudaGetSymbolAddress((void**)&pWs3, g_Ws3);

    const int nScanBlocks = cdivl(N, 256);           // 391
    const int half = (int)((N / 2 + 63) & ~63);      // 50048
    const int gemmBlocksA = half / 64;               // 782
    const int gemmBlocksB = cdivl(N - half, 64);     // 781
    const int gemmBlocksFull = cdivl(N, 64);         // 1563
    const int edgeBlocks4 = cdivl(E, 1024);          // 1563 (4 edges/thread)

    // dynamic smem: XN==2 -> single A array; XN==3 -> two A arrays
    const int SMEM192_X2 = (64 * 36 + 2 * 32 * 200) * 4;     // 60416
    const int SMEM64_X2  = (64 * 36 + 2 * 32 * 72) * 4;      // 27648
    const int SMEM128_X3 = (2 * 64 * 36 + 2 * 32 * 136) * 4; // 53248
    cudaFuncSetAttribute(fused_gemmA_hist, cudaFuncAttributeMaxDynamicSharedMemorySize, SMEM192_X2);
    cudaFuncSetAttribute(fused_gemmB_scatter, cudaFuncAttributeMaxDynamicSharedMemorySize, SMEM192_X2);
    cudaFuncSetAttribute(gemm_tf32_kernel<192, 64, true, true, false, 2>,
                         cudaFuncAttributeMaxDynamicSharedMemorySize, SMEM64_X2);
    cudaFuncSetAttribute(gemm_tf32_kernel<192, 128, true, true, true, 3>,
                         cudaFuncAttributeMaxDynamicSharedMemorySize, SMEM128_X3);

    // #0: weight transform + split
    wsplit_kernel<<<240, 256>>>(W1, W2, W3);
    // #1: L1 GEMM half-A + histogram (hidden, 4 edges/thread)
    fused_gemmA_hist<<<gemmBlocksA + edgeBlocks4, 256, SMEM192_X2>>>(x, pG, (int)N, ei, ea, E, gemmBlocksA);
    // #2, #3: 2-level parallel scan
    scan_local_kernel<<<nScanBlocks, 256>>>((int)N);
    scan_finish_kernel<<<nScanBlocks, 256>>>((int)N, (int)E);
    // #4: L1 GEMM half-B + CSR scatter (hidden, 4 edges/thread)
    fused_gemmB_scatter<<<gemmBlocksB + edgeBlocks4, 256, SMEM192_X2>>>(x, pG, (int)N, half, ei, ea, E, gemmBlocksB);

    // ---- Layer 1 props: H1 = relu(C + P(U1 + P(U2)) + b1) ----
    prop64_kernel<true, false><<<cdivl(N * 16, 256), 256>>>(pG + 128, 192, pG + 64, 192, nullptr, pTA, (int)N);
    prop64_kernel<true, true><<<cdivl(N * 16, 256), 256>>>(pTA, 64, pG, 192, b1, pH1, (int)N);

    // ---- Layer 2 (x2 GEMM) ----
    prop64_kernel<false, false><<<cdivl(N * 16, 256), 256>>>(pH1, 64, nullptr, 0, nullptr, pTA, (int)N);
    prop64_kernel<false, false><<<cdivl(N * 16, 256), 256>>>(pTA, 64, nullptr, 0, nullptr, pTB, (int)N);
    gemm_tf32_kernel<192, 64, true, true, false, 2><<<gemmBlocksFull, 256, SMEM64_X2>>>(
        pH1, pTA, pTB, pWb2, pWs2, b2, pH2, nullptr, (int)N, 0);

    // ---- Layer 3 (x3 GEMM, fused mean-pool) ----
    prop64_kernel<false, false><<<cdivl(N * 16, 256), 256>>>(pH2, 64, nullptr, 0, nullptr, pTA, (int)N);
    prop64_kernel<false, false><<<cdivl(N * 16, 256), 256>>>(pTA, 64, nullptr, 0, nullptr, pTB, (int)N);
    gemm_tf32_kernel<192, 128, true, true, true, 3><<<gemmBlocksFull, 256, SMEM128_X3>>>(
        pH2, pTA, pTB, pWb3, pWs3, b3, nullptr, bat, (int)N, 0);

    // ---- head (restores sums/cnt) ----
    final_kernel<<<NG, 32>>>(linW, linB, out);
}

// round 17
// speedup vs baseline: 1.0620x; 1.0620x over previous
#include <cuda_runtime.h>
#include <cuda_bf16.h>
#include <stdint.h>

#define NN 100000
#define NE 1600000
#define NG 64

typedef unsigned int uint32;

// ---------------- static device scratch (zero-initialized at load; restored each run) ----------------
static __device__ float g_deg[NN];
static __device__ int   g_cnti[NN];
static __device__ int   g_rowptr[NN + 1];
static __device__ int   g_offs[NN];
static __device__ int   g_bsum[512];
static __device__ int   g_is64;
static __device__ int2  g_csr[NE];                 // packed {src, w_bits}
static __device__ float g_G[(size_t)NN * 192];
static __device__ float g_TA[(size_t)NN * 64];
static __device__ float g_TB[(size_t)NN * 64];
static __device__ float g_H1[(size_t)NN * 64];
static __device__ float g_H2[(size_t)NN * 64];
static __device__ float g_sums[NG * 128];
static __device__ float g_cnt[NG];
static __device__ float g_Wb1[128 * 192];
static __device__ float g_Ws1[128 * 192];
static __device__ float g_Wb2[192 * 64];
static __device__ float g_Ws2[192 * 64];
static __device__ float g_Wb3[192 * 128];
static __device__ float g_Ws3[192 * 128];

// ---------------- helpers ----------------
__device__ __forceinline__ long ldidx(const void* p, long i, int is64) {
    if (is64) return (long)((const long long*)p)[i];
    return (long)((const int*)p)[i];
}

// Detect int64 vs int32 from edge_index words (uniform random values -> safe).
// NEVER call on `batch` (sorted, leading zeros break the heuristic).
__device__ __forceinline__ int detect64(const unsigned int* w) {
    int is64 = 1;
    for (int i = 0; i < 128; i++) {
        if (w[2 * i + 1] != 0u) { is64 = 0; break; }
    }
    return is64;
}

__device__ __forceinline__ float rinv(float d) { return (d > 0.0f) ? rsqrtf(d) : 0.0f; }

__device__ __forceinline__ void redAdd2(float* p, float x, float y) {
    asm volatile("red.global.add.v2.f32 [%0], {%1, %2};"
                 :: "l"(p), "f"(x), "f"(y) : "memory");
}

__device__ __forceinline__ uint32 tf32r(float f) {
    uint32 r;
    asm("cvt.rna.tf32.f32 %0, %1;" : "=r"(r) : "f"(f));
    return r;
}

__device__ __forceinline__ void mma_tf32(float* c, const uint32* a, uint32 b0, uint32 b1) {
    asm volatile("mma.sync.aligned.m16n8k8.row.col.f32.tf32.tf32.f32 "
                 "{%0,%1,%2,%3}, {%4,%5,%6,%7}, {%8,%9}, {%0,%1,%2,%3};"
                 : "+f"(c[0]), "+f"(c[1]), "+f"(c[2]), "+f"(c[3])
                 : "r"(a[0]), "r"(a[1]), "r"(a[2]), "r"(a[3]), "r"(b0), "r"(b1));
}

__device__ __forceinline__ void split1(float f, float& fb, float& fs) {
    uint32 tb = tf32r(f);
    fb = __uint_as_float(tb);
    fs = __uint_as_float(tf32r(f - fb));
}

// ---------------- tf32 tensor-core GEMM body (XN=3: full 3xTF32; XN=2: drop A-small term) ----------------
// POOLB: apply bias+relu and pool directly into g_sums/g_cnt, restore deg/cnti invariants.
template <int KTOT, int BN, bool TRIPLE, bool RELUB, bool POOLB, int XN>
__device__ __forceinline__ void gemm_tf32_body(
    int bid, const float* __restrict__ A0, const float* __restrict__ A1,
    const float* __restrict__ A2,
    const float* __restrict__ Wb, const float* __restrict__ Ws,
    const float* __restrict__ bias, float* __restrict__ out,
    const void* __restrict__ batch, int N, int nodeOff) {
    constexpr int BM = 64, BK = 32;
    constexpr int SAS = 36;
    constexpr int SBS = BN + 8;
    constexpr int NA = BN / 32;
    extern __shared__ float sm[];
    float* sAb = sm;
    float* sAs = (XN == 3) ? (sAb + BM * SAS) : sAb;   // unused alias when XN==2
    float* sBb = sAb + (XN == 3 ? 2 : 1) * BM * SAS;
    float* sBs = sBb + BK * SBS;

    const int tid = threadIdx.x;
    const int wid = tid >> 5, lane = tid & 31;
    const int g = lane >> 2, tig = lane & 3;
    const int wm = (wid & 1) * 32;
    const int wn = (wid >> 1) * (BN / 4);
    const int base = nodeOff + bid * BM;

    float acc[2][NA][4];
#pragma unroll
    for (int ma = 0; ma < 2; ma++)
#pragma unroll
        for (int j = 0; j < NA; j++)
#pragma unroll
            for (int i = 0; i < 4; i++) acc[ma][j][i] = 0.f;

    for (int kc = 0; kc < KTOT; kc += BK) {
        const float* Ap;
        int strideA, colBase;
        if (TRIPLE) {
            const float* Ts[3] = {A0, A1, A2};
            Ap = Ts[kc >> 6]; strideA = 64; colBase = kc & 63;
        } else {
            Ap = A0; strideA = KTOT; colBase = kc;
        }
#pragma unroll
        for (int r = 0; r < 2; r++) {
            int i = tid + r * 256;
            int row = i >> 3, c4 = (i & 7) * 4;
            int node = base + row;
            float4 v = (node < N)
                ? *reinterpret_cast<const float4*>(Ap + (size_t)node * strideA + colBase + c4)
                : make_float4(0.f, 0.f, 0.f, 0.f);
            if (XN == 3) {
                float4 vb, vs;
                split1(v.x, vb.x, vs.x); split1(v.y, vb.y, vs.y);
                split1(v.z, vb.z, vs.z); split1(v.w, vb.w, vs.w);
                *reinterpret_cast<float4*>(&sAb[row * SAS + c4]) = vb;
                *reinterpret_cast<float4*>(&sAs[row * SAS + c4]) = vs;
            } else {
                float4 vb;
                vb.x = __uint_as_float(tf32r(v.x));
                vb.y = __uint_as_float(tf32r(v.y));
                vb.z = __uint_as_float(tf32r(v.z));
                vb.w = __uint_as_float(tf32r(v.w));
                *reinterpret_cast<float4*>(&sAb[row * SAS + c4]) = vb;
            }
        }
#pragma unroll
        for (int i = tid; i < BK * BN / 4; i += 256) {
            int row = i / (BN / 4), c4 = (i % (BN / 4)) * 4;
            *reinterpret_cast<float4*>(&sBb[row * SBS + c4]) =
                *reinterpret_cast<const float4*>(Wb + (size_t)(kc + row) * BN + c4);
            *reinterpret_cast<float4*>(&sBs[row * SBS + c4]) =
                *reinterpret_cast<const float4*>(Ws + (size_t)(kc + row) * BN + c4);
        }
        __syncthreads();
#pragma unroll
        for (int ks = 0; ks < 4; ks++) {
            const int k0 = ks * 8;
            uint32 ab[2][4], as_[2][4];
#pragma unroll
            for (int ma = 0; ma < 2; ma++) {
                const float* pb = &sAb[(wm + ma * 16 + g) * SAS + k0 + tig];
                ab[ma][0] = __float_as_uint(pb[0]);
                ab[ma][1] = __float_as_uint(pb[8 * SAS]);
                ab[ma][2] = __float_as_uint(pb[4]);
                ab[ma][3] = __float_as_uint(pb[8 * SAS + 4]);
                if (XN == 3) {
                    const float* ps = &sAs[(wm + ma * 16 + g) * SAS + k0 + tig];
                    as_[ma][0] = __float_as_uint(ps[0]);
                    as_[ma][1] = __float_as_uint(ps[8 * SAS]);
                    as_[ma][2] = __float_as_uint(ps[4]);
                    as_[ma][3] = __float_as_uint(ps[8 * SAS + 4]);
                }
            }
#pragma unroll
            for (int j = 0; j < NA; j++) {
                int n = wn + j * 8 + g;
                uint32 bb0 = __float_as_uint(sBb[(k0 + tig) * SBS + n]);
                uint32 bb1 = __float_as_uint(sBb[(k0 + tig + 4) * SBS + n]);
                uint32 bs0 = __float_as_uint(sBs[(k0 + tig) * SBS + n]);
                uint32 bs1 = __float_as_uint(sBs[(k0 + tig + 4) * SBS + n]);
#pragma unroll
                for (int ma = 0; ma < 2; ma++) {
                    mma_tf32(acc[ma][j], ab[ma], bs0, bs1);                 // big * small
                    if (XN == 3) mma_tf32(acc[ma][j], as_[ma], bb0, bb1);   // small * big
                    mma_tf32(acc[ma][j], ab[ma], bb0, bb1);                 // big * big
                }
            }
        }
        __syncthreads();
    }

    // ---- epilogue ----
    const int is64 = POOLB ? g_is64 : 0;
#pragma unroll
    for (int ma = 0; ma < 2; ma++) {
        const int n0 = base + wm + ma * 16 + g, n1 = n0 + 8;
        int g0 = -1, g1 = -1;
        if (POOLB) {
            if (n0 < N) g0 = (int)ldidx(batch, n0, is64);
            if (n1 < N) g1 = (int)ldidx(batch, n1, is64);
        }
#pragma unroll
        for (int j = 0; j < NA; j++) {
            int col = wn + j * 8 + tig * 2;
            float c0 = acc[ma][j][0], c1 = acc[ma][j][1], c2 = acc[ma][j][2], c3 = acc[ma][j][3];
            if (RELUB) {
                float b0 = bias[col], b1 = bias[col + 1];
                c0 = fmaxf(c0 + b0, 0.f); c1 = fmaxf(c1 + b1, 0.f);
                c2 = fmaxf(c2 + b0, 0.f); c3 = fmaxf(c3 + b1, 0.f);
            }
            if (POOLB) {
                if (n0 < N) redAdd2(&g_sums[g0 * 128 + col], c0, c1);
                if (n1 < N) redAdd2(&g_sums[g1 * 128 + col], c2, c3);
            } else {
                if (n0 < N) *reinterpret_cast<float2*>(&out[(size_t)n0 * BN + col]) = make_float2(c0, c1);
                if (n1 < N) *reinterpret_cast<float2*>(&out[(size_t)n1 * BN + col]) = make_float2(c2, c3);
            }
        }
        if (POOLB && wn == 0 && tig == 0) {
            if (n0 < N) atomicAdd(&g_cnt[g0], 1.0f);
            if (n1 < N) atomicAdd(&g_cnt[g1], 1.0f);
        }
    }
    if (POOLB) {
        if (tid < BM) {
            int node = base + tid;
            if (node < N) { g_deg[node] = 0.0f; g_cnti[node] = 0; }
        }
    }
}

template <int KTOT, int BN, bool TRIPLE, bool RELUB, bool POOLB, int XN>
__global__ void gemm_tf32_kernel(const float* __restrict__ A0, const float* __restrict__ A1,
                                 const float* __restrict__ A2,
                                 const float* __restrict__ Wb, const float* __restrict__ Ws,
                                 const float* __restrict__ bias, float* __restrict__ out,
                                 const void* __restrict__ batch, int N, int nodeOff) {
    gemm_tf32_body<KTOT, BN, TRIPLE, RELUB, POOLB, XN>(blockIdx.x, A0, A1, A2, Wb, Ws, bias, out,
                                                       batch, N, nodeOff);
}

// ---------------- launch #0: weight transform + tf32 split ----------------
__global__ void wsplit_kernel(const float* __restrict__ W1, const float* __restrict__ W2,
                              const float* __restrict__ W3) {
    int i = blockIdx.x * blockDim.x + threadIdx.x;
    float v;
    float *pb, *ps;
    int idx;
    if (i < 128 * 192) {
        int f = i / 192, n = i % 192, chunk = n >> 6, nc = n & 63;
        const int S = 128 * 64;
        if (chunk == 0)      v = W1[f * 64 + nc] - W1[2 * S + f * 64 + nc];
        else if (chunk == 1) v = W1[S + f * 64 + nc];
        else                 v = 2.f * W1[2 * S + f * 64 + nc];
        pb = g_Wb1; ps = g_Ws1; idx = i;
    } else if (i < 128 * 192 + 192 * 64) {
        int j = i - 128 * 192;
        int k = j / 64, n = j % 64, seg = k / 64, f = k % 64;
        const int S = 64 * 64;
        if (seg == 0)      v = W2[f * 64 + n] - W2[2 * S + f * 64 + n];
        else if (seg == 1) v = W2[S + f * 64 + n];
        else               v = 2.f * W2[2 * S + f * 64 + n];
        pb = g_Wb2; ps = g_Ws2; idx = j;
    } else if (i < 128 * 192 + 192 * 64 + 192 * 128) {
        int j = i - 128 * 192 - 192 * 64;
        int k = j / 128, n = j % 128, seg = k / 64, f = k % 64;
        const int S = 64 * 128;
        if (seg == 0)      v = W3[f * 128 + n] - W3[2 * S + f * 128 + n];
        else if (seg == 1) v = W3[S + f * 128 + n];
        else               v = 2.f * W3[2 * S + f * 128 + n];
        pb = g_Wb3; ps = g_Ws3; idx = j;
    } else return;
    float fb, fs;
    split1(v, fb, fs);
    pb[idx] = fb;
    ps[idx] = fs;
}

// ---------------- launch #1: L1 GEMM half-A + histogram (4 edges/thread) ----------------
__global__ void fused_gemmA_hist(const float* __restrict__ x, float* __restrict__ G, int N,
                                 const void* __restrict__ ei, const float* __restrict__ ea,
                                 long E, int gemmBlocks) {
    if (blockIdx.x < gemmBlocks) {
        gemm_tf32_body<128, 192, false, false, false, 2>(blockIdx.x, x, nullptr, nullptr,
                                                         g_Wb1, g_Ws1, nullptr, G, nullptr, N, 0);
        return;
    }
    __shared__ int s64;
    if (threadIdx.x == 0) {
        s64 = detect64((const unsigned int*)ei);
        if (blockIdx.x == gemmBlocks) g_is64 = s64;   // publish for pooled epilogue
    }
    __syncthreads();
    long eBase = (long)(blockIdx.x - gemmBlocks) * 1024;
#pragma unroll
    for (int k = 0; k < 4; k++) {
        long e = eBase + threadIdx.x + k * 256;
        if (e < E) {
            long src = ldidx(ei, e, s64);
            long dst = ldidx(ei, E + e, s64);
            atomicAdd(&g_deg[src], ea[e]);
            atomicAdd(&g_cnti[dst], 1);
        }
    }
}

// ---------------- launches #2/#3: 2-level exclusive scan (parallel) ----------------
__global__ void scan_local_kernel(int n) {
    __shared__ int sm[256];
    int gid = blockIdx.x * 256 + threadIdx.x;
    int v = (gid < n) ? g_cnti[gid] : 0;
    sm[threadIdx.x] = v;
    __syncthreads();
    for (int off = 1; off < 256; off <<= 1) {
        int t = (threadIdx.x >= off) ? sm[threadIdx.x - off] : 0;
        __syncthreads();
        sm[threadIdx.x] += t;
        __syncthreads();
    }
    if (gid < n) g_rowptr[gid] = sm[threadIdx.x] - v;
    if (threadIdx.x == 255) g_bsum[blockIdx.x] = sm[255];
}

__global__ void scan_finish_kernel(int n, int E) {
    __shared__ int red[256];
    const int bid = blockIdx.x;
    int partial = 0;
    for (int i = threadIdx.x; i < bid; i += 256) partial += g_bsum[i];
    red[threadIdx.x] = partial;
    __syncthreads();
    for (int off = 128; off > 0; off >>= 1) {
        if (threadIdx.x < off) red[threadIdx.x] += red[threadIdx.x + off];
        __syncthreads();
    }
    int offset = red[0];
    int gid = bid * 256 + threadIdx.x;
    if (gid < n) {
        int v = g_rowptr[gid] + offset;
        g_rowptr[gid] = v;
        g_offs[gid] = v;
    }
    if (gid == 0) g_rowptr[n] = E;
}

// ---------------- launch #4: L1 GEMM half-B + CSR scatter (4 edges/thread, packed int2) ----------------
__global__ void fused_gemmB_scatter(const float* __restrict__ x, float* __restrict__ G, int N,
                                    int nodeOff, const void* __restrict__ ei,
                                    const float* __restrict__ ea, long E, int gemmBlocks) {
    if (blockIdx.x < gemmBlocks) {
        gemm_tf32_body<128, 192, false, false, false, 2>(blockIdx.x, x, nullptr, nullptr,
                                                         g_Wb1, g_Ws1, nullptr, G, nullptr, N, nodeOff);
        return;
    }
    __shared__ int s64;
    if (threadIdx.x == 0) s64 = detect64((const unsigned int*)ei);
    __syncthreads();
    long eBase = (long)(blockIdx.x - gemmBlocks) * 1024;
#pragma unroll
    for (int k = 0; k < 4; k++) {
        long e = eBase + threadIdx.x + k * 256;
        if (e < E) {
            int src = (int)ldidx(ei, e, s64);
            int dst = (int)ldidx(ei, E + e, s64);
            int pos = atomicAdd(&g_offs[dst], 1);
            float w = -rinv(g_deg[src]) * ea[e] * rinv(g_deg[dst]);
            g_csr[pos] = make_int2(src, __float_as_int(w));
        }
    }
}

// ---------------- dst-major pull propagation, F=64, unroll-8, (256,5) proven optimum ----------------
template <bool ADD, bool RELUB>
__global__ void __launch_bounds__(256, 5)
prop64_kernel(const float* __restrict__ x, int xs,
              const float* __restrict__ add, int as,
              const float* __restrict__ bias,
              float* __restrict__ out, int N) {
    int t = blockIdx.x * blockDim.x + threadIdx.x;
    int n = t >> 4;
    int c = t & 15;
    if (n >= N) return;
    int p = g_rowptr[n], end = g_rowptr[n + 1];
    float4 a0 = {0.f, 0.f, 0.f, 0.f}, a1 = {0.f, 0.f, 0.f, 0.f};
    float4 a2 = {0.f, 0.f, 0.f, 0.f}, a3 = {0.f, 0.f, 0.f, 0.f};
    for (; p + 8 <= end; p += 8) {
        int2 e0 = __ldg(&g_csr[p]),     e1 = __ldg(&g_csr[p + 1]);
        int2 e2 = __ldg(&g_csr[p + 2]), e3 = __ldg(&g_csr[p + 3]);
        int2 e4 = __ldg(&g_csr[p + 4]), e5 = __ldg(&g_csr[p + 5]);
        int2 e6 = __ldg(&g_csr[p + 6]), e7 = __ldg(&g_csr[p + 7]);
        float4 v0 = __ldg(reinterpret_cast<const float4*>(x + (size_t)e0.x * xs) + c);
        float4 v1 = __ldg(reinterpret_cast<const float4*>(x + (size_t)e1.x * xs) + c);
        float4 v2 = __ldg(reinterpret_cast<const float4*>(x + (size_t)e2.x * xs) + c);
        float4 v3 = __ldg(reinterpret_cast<const float4*>(x + (size_t)e3.x * xs) + c);
        float4 v4 = __ldg(reinterpret_cast<const float4*>(x + (size_t)e4.x * xs) + c);
        float4 v5 = __ldg(reinterpret_cast<const float4*>(x + (size_t)e5.x * xs) + c);
        float4 v6 = __ldg(reinterpret_cast<const float4*>(x + (size_t)e6.x * xs) + c);
        float4 v7 = __ldg(reinterpret_cast<const float4*>(x + (size_t)e7.x * xs) + c);
        float w0 = __int_as_float(e0.y), w1 = __int_as_float(e1.y);
        float w2 = __int_as_float(e2.y), w3 = __int_as_float(e3.y);
        float w4 = __int_as_float(e4.y), w5 = __int_as_float(e5.y);
        float w6 = __int_as_float(e6.y), w7 = __int_as_float(e7.y);
        a0.x += w0 * v0.x; a0.y += w0 * v0.y; a0.z += w0 * v0.z; a0.w += w0 * v0.w;
        a1.x += w1 * v1.x; a1.y += w1 * v1.y; a1.z += w1 * v1.z; a1.w += w1 * v1.w;
        a2.x += w2 * v2.x; a2.y += w2 * v2.y; a2.z += w2 * v2.z; a2.w += w2 * v2.w;
        a3.x += w3 * v3.x; a3.y += w3 * v3.y; a3.z += w3 * v3.z; a3.w += w3 * v3.w;
        a0.x += w4 * v4.x; a0.y += w4 * v4.y; a0.z += w4 * v4.z; a0.w += w4 * v4.w;
        a1.x += w5 * v5.x; a1.y += w5 * v5.y; a1.z += w5 * v5.z; a1.w += w5 * v5.w;
        a2.x += w6 * v6.x; a2.y += w6 * v6.y; a2.z += w6 * v6.z; a2.w += w6 * v6.w;
        a3.x += w7 * v7.x; a3.y += w7 * v7.y; a3.z += w7 * v7.z; a3.w += w7 * v7.w;
    }
    for (; p < end; p++) {
        int2 e0 = __ldg(&g_csr[p]);
        float w0 = __int_as_float(e0.y);
        float4 v0 = __ldg(reinterpret_cast<const float4*>(x + (size_t)e0.x * xs) + c);
        a0.x += w0 * v0.x; a0.y += w0 * v0.y; a0.z += w0 * v0.z; a0.w += w0 * v0.w;
    }
    a0.x += a1.x; a0.y += a1.y; a0.z += a1.z; a0.w += a1.w;
    a2.x += a3.x; a2.y += a3.y; a2.z += a3.z; a2.w += a3.w;
    a0.x += a2.x; a0.y += a2.y; a0.z += a2.z; a0.w += a2.w;
    if (ADD) {
        float4 u = __ldg(reinterpret_cast<const float4*>(add + (size_t)n * as) + c);
        a0.x += u.x; a0.y += u.y; a0.z += u.z; a0.w += u.w;
    }
    if (RELUB) {
        float4 b = *reinterpret_cast<const float4*>(bias + 4 * c);
        a0.x = fmaxf(a0.x + b.x, 0.f);
        a0.y = fmaxf(a0.y + b.y, 0.f);
        a0.z = fmaxf(a0.z + b.z, 0.f);
        a0.w = fmaxf(a0.w + b.w, 0.f);
    }
    reinterpret_cast<float4*>(out + (size_t)n * 64)[c] = a0;
}

// ---------------- final linear + restore sums/cnt to zero ----------------
__global__ void final_kernel(const float* __restrict__ lw, const float* __restrict__ lb,
                             float* __restrict__ out) {
    __shared__ float sp[128];
    int g = blockIdx.x;
    float inv = 1.0f / fmaxf(g_cnt[g], 1.0f);
    for (int i = threadIdx.x; i < 128; i += 32)
        sp[i] = g_sums[g * 128 + i] * inv;
    __syncthreads();
    if (threadIdx.x < 10) {
        float acc = lb[threadIdx.x];
#pragma unroll 8
        for (int f = 0; f < 128; f++)
            acc += sp[f] * lw[f * 10 + threadIdx.x];
        out[g * 10 + threadIdx.x] = acc;
    }
    for (int i = threadIdx.x; i < 128; i += 32)
        g_sums[g * 128 + i] = 0.0f;
    if (threadIdx.x == 0) g_cnt[g] = 0.0f;
}

static inline int cdivl(long a, long b) { return (int)((a + b - 1) / b); }

extern "C" void kernel_launch(void* const* d_in, const int* in_sizes, int n_in,
                              void* d_out, int out_size) {
    const float* x    = (const float*)d_in[0];
    const void*  ei   = d_in[1];
    const float* ea   = (const float*)d_in[2];
    const void*  bat  = d_in[3];
    const float* W1   = (const float*)d_in[4];
    const float* b1   = (const float*)d_in[5];
    const float* W2   = (const float*)d_in[6];
    const float* b2   = (const float*)d_in[7];
    const float* W3   = (const float*)d_in[8];
    const float* b3   = (const float*)d_in[9];
    const float* linW = (const float*)d_in[10];
    const float* linB = (const float*)d_in[11];
    float* out = (float*)d_out;

    const long E = in_sizes[2];
    const long N = in_sizes[3];

    float *pG, *pTA, *pTB, *pH1, *pH2;
    float *pWb2, *pWs2, *pWb3, *pWs3;
    cudaGetSymbolAddress((void**)&pG, g_G);
    cudaGetSymbolAddress((void**)&pTA, g_TA);
    cudaGetSymbolAddress((void**)&pTB, g_TB);
    cudaGetSymbolAddress((void**)&pH1, g_H1);
    cudaGetSymbolAddress((void**)&pH2, g_H2);
    cudaGetSymbolAddress((void**)&pWb2, g_Wb2);
    cudaGetSymbolAddress((void**)&pWs2, g_Ws2);
    cudaGetSymbolAddress((void**)&pWb3, g_Wb3);
    cudaGetSymbolAddress((void**)&pWs3, g_Ws3);

    const int nScanBlocks = cdivl(N, 256);           // 391
    const int half = (int)((N / 2 + 63) & ~63);      // 50048
    const int gemmBlocksA = half / 64;               // 782
    const int gemmBlocksB = cdivl(N - half, 64);     // 781
    const int gemmBlocksFull = cdivl(N, 64);         // 1563
    const int edgeBlocks4 = cdivl(E, 1024);          // 1563 (4 edges/thread)

    // dynamic smem: XN==2 -> single A array; XN==3 -> two A arrays
    const int SMEM192_X2 = (64 * 36 + 2 * 32 * 200) * 4;     // 60416
    const int SMEM64_X2  = (64 * 36 + 2 * 32 * 72) * 4;      // 27648
    const int SMEM128_X3 = (2 * 64 * 36 + 2 * 32 * 136) * 4; // 53248
    cudaFuncSetAttribute(fused_gemmA_hist, cudaFuncAttributeMaxDynamicSharedMemorySize, SMEM192_X2);
    cudaFuncSetAttribute(fused_gemmB_scatter, cudaFuncAttributeMaxDynamicSharedMemorySize, SMEM192_X2);
    cudaFuncSetAttribute(gemm_tf32_kernel<192, 64, true, true, false, 2>,
                         cudaFuncAttributeMaxDynamicSharedMemorySize, SMEM64_X2);
    cudaFuncSetAttribute(gemm_tf32_kernel<192, 128, true, true, true, 3>,
                         cudaFuncAttributeMaxDynamicSharedMemorySize, SMEM128_X3);

    // #0: weight transform + split
    wsplit_kernel<<<240, 256>>>(W1, W2, W3);
    // #1: L1 GEMM half-A + histogram (hidden, 4 edges/thread)
    fused_gemmA_hist<<<gemmBlocksA + edgeBlocks4, 256, SMEM192_X2>>>(x, pG, (int)N, ei, ea, E, gemmBlocksA);
    // #2, #3: 2-level parallel scan
    scan_local_kernel<<<nScanBlocks, 256>>>((int)N);
    scan_finish_kernel<<<nScanBlocks, 256>>>((int)N, (int)E);
    // #4: L1 GEMM half-B + CSR scatter (hidden, 4 edges/thread)
    fused_gemmB_scatter<<<gemmBlocksB + edgeBlocks4, 256, SMEM192_X2>>>(x, pG, (int)N, half, ei, ea, E, gemmBlocksB);

    // ---- Layer 1 props: H1 = relu(C + P(U1 + P(U2)) + b1) ----
    prop64_kernel<true, false><<<cdivl(N * 16, 256), 256>>>(pG + 128, 192, pG + 64, 192, nullptr, pTA, (int)N);
    prop64_kernel<true, true><<<cdivl(N * 16, 256), 256>>>(pTA, 64, pG, 192, b1, pH1, (int)N);

    // ---- Layer 2 (x2 GEMM) ----
    prop64_kernel<false, false><<<cdivl(N * 16, 256), 256>>>(pH1, 64, nullptr, 0, nullptr, pTA, (int)N);
    prop64_kernel<false, false><<<cdivl(N * 16, 256), 256>>>(pTA, 64, nullptr, 0, nullptr, pTB, (int)N);
    gemm_tf32_kernel<192, 64, true, true, false, 2><<<gemmBlocksFull, 256, SMEM64_X2>>>(
        pH1, pTA, pTB, pWb2, pWs2, b2, pH2, nullptr, (int)N, 0);

    // ---- Layer 3 (x3 GEMM, fused mean-pool) ----
    prop64_kernel<false, false><<<cdivl(N * 16, 256), 256>>>(pH2, 64, nullptr, 0, nullptr, pTA, (int)N);
    prop64_kernel<false, false><<<cdivl(N * 16, 256), 256>>>(pTA, 64, nullptr, 0, nullptr, pTB, (int)N);
    gemm_tf32_kernel<192, 128, true, true, true, 3><<<gemmBlocksFull, 256, SMEM128_X3>>>(
        pH2, pTA, pTB, pWb3, pWs3, b3, nullptr, bat, (int)N, 0);

    // ---- head (restores sums/cnt) ----
    final_kernel<<<NG, 32>>>(linW, linB, out);
}